// round 16
// baseline (speedup 1.0000x reference)
#include <cuda_runtime.h>
#include <cuda_fp16.h>
#include <math.h>
#include <stdint.h>

#define BB 64
#define TT 2048
#define DD 512
#define UU 512

// ---------------- device scratch ----------------
__device__ float g_comb[BB * UU];
__device__ float g_spart[2 * BB * TT];
// A fragments: [b][t16 0..127][k16 0..31][lane 0..31] -> uint4 (a0,a1,a2,a3) fp16x2
__device__ uint4 g_afrag[BB * 128 * 32 * 32];
// B fragments (fp16, 2 n8 per uint4): [n4 0..31][k16 0..31][lane 0..31]
__device__ uint4 g_bfrag[32 * 32 * 32];

// ---------------- helpers ----------------
__device__ __forceinline__ uint32_t pack_h2(float x, float y) {
    __half2 h = __floats2half2_rn(x, y);
    return *(uint32_t*)&h;
}

__device__ __forceinline__ float tanh_fast(float x) {
    float y;
    asm("tanh.approx.f32 %0, %1;" : "=f"(y) : "f"(x));
    return y;
}

__device__ __forceinline__ void mma_f16(float* d, const uint4& a, uint32_t b0, uint32_t b1) {
    asm volatile(
        "mma.sync.aligned.m16n8k16.row.col.f32.f16.f16.f32 "
        "{%0,%1,%2,%3}, {%4,%5,%6,%7}, {%8,%9}, {%0,%1,%2,%3};"
        : "+f"(d[0]), "+f"(d[1]), "+f"(d[2]), "+f"(d[3])
        : "r"(a.x), "r"(a.y), "r"(a.z), "r"(a.w), "r"(b0), "r"(b1));
}

// ---------------- prep_all: afrag (blocks 0..32767) + bfrag (32768..32895) + comb (32896..32959) ----------------
__global__ void __launch_bounds__(256)
prep_all_kernel(const float* __restrict__ feat,
                const float* __restrict__ W1,
                const float* __restrict__ hidden,
                const float* __restrict__ W2,
                const float* __restrict__ W1b,
                const float* __restrict__ W2b) {
    int blk = blockIdx.x;
    int tid = threadIdx.x;

    if (blk < 32768) {
        // ---- A fragments: features fp32 -> fp16 fragment-major ----
        int gidx = blk * 256 + tid;                 // 8388608
        int lane = gidx & 31;
        int k16 = (gidx >> 5) & 31;
        int t16 = (gidx >> 10) & 127;
        int b = gidx >> 17;
        int g = lane >> 2, tg = lane & 3;
        int tA = t16 * 16 + g;
        int kA = k16 * 16 + 2 * tg;
        const float* base = feat + ((size_t)b * TT) * DD;
        float2 f00 = *(const float2*)(base + (size_t)tA * DD + kA);
        float2 f10 = *(const float2*)(base + (size_t)(tA + 8) * DD + kA);
        float2 f01 = *(const float2*)(base + (size_t)tA * DD + kA + 8);
        float2 f11 = *(const float2*)(base + (size_t)(tA + 8) * DD + kA + 8);
        uint4 o;
        o.x = pack_h2(f00.x, f00.y);
        o.y = pack_h2(f10.x, f10.y);
        o.z = pack_h2(f01.x, f01.y);
        o.w = pack_h2(f11.x, f11.y);
        g_afrag[gidx] = o;
    } else if (blk < 32896) {
        // ---- B fragments: W1 -> fp16 fragment-major (2 n8 per uint4) ----
        int gidx = (blk - 32768) * 256 + tid;       // 32768
        int lane = gidx & 31;
        int k16 = (gidx >> 5) & 31;
        int n4 = gidx >> 10;
        int g = lane >> 2, tg = lane & 3;
        int k = k16 * 16 + 2 * tg;
        int ua = (2 * n4) * 8 + g;
        int ub = (2 * n4 + 1) * 8 + g;
        uint4 o;
        o.x = pack_h2(W1[(size_t)k * UU + ua],       W1[(size_t)(k + 1) * UU + ua]);
        o.y = pack_h2(W1[(size_t)(k + 8) * UU + ua], W1[(size_t)(k + 9) * UU + ua]);
        o.z = pack_h2(W1[(size_t)k * UU + ub],       W1[(size_t)(k + 1) * UU + ub]);
        o.w = pack_h2(W1[(size_t)(k + 8) * UU + ub], W1[(size_t)(k + 9) * UU + ub]);
        g_bfrag[gidx] = o;
    } else {
        // ---- comb[b][u], 256 threads handle 512 u ----
        int b = blk - 32896;
        __shared__ float h[DD];
        h[tid] = hidden[b * DD + tid];
        h[tid + 256] = hidden[b * DD + tid + 256];
        __syncthreads();
#pragma unroll
        for (int rep = 0; rep < 2; ++rep) {
            int u = tid + rep * 256;
            float acc = W1b[u] + W2b[u];
#pragma unroll 8
            for (int d = 0; d < DD; ++d)
                acc = fmaf(h[d], W2[d * UU + u], acc);
            g_comb[b * UU + u] = acc;
        }
    }
}

// ---------------- score GEMM: R12 winner (byte-identical) ----------------
__global__ void __launch_bounds__(512)
score_kernel(const float* __restrict__ Vw) {
    __shared__ float comb_s[256];
    __shared__ float v_s[256];
    __shared__ float srow[128];

    int tid = threadIdx.x;
    int wid = tid >> 5, lane = tid & 31;
    int warpM = wid & 3, warpN = wid >> 2;
    int g = lane >> 2, tg = lane & 3;

    int nchunk = blockIdx.x;
    int t0 = blockIdx.y << 7;
    int b = blockIdx.z;
    int u0 = nchunk << 8;

    if (tid < 256) {
        comb_s[tid] = g_comb[b * UU + u0 + tid];
        v_s[tid] = Vw[u0 + tid];
    }
    if (tid < 128) srow[tid] = 0.f;

    int tt0 = (t0 >> 4) + warpM * 2;
    const uint4* pA0 = g_afrag + (((size_t)(b * 128 + tt0) * 32) * 32 + lane);
    const uint4* pA1 = pA0 + 32 * 32;
    const uint4* pB  = g_bfrag + (((size_t)(nchunk * 16 + warpN * 4) * 32) * 32 + lane);

    float acc[2][8][4];
#pragma unroll
    for (int i = 0; i < 2; ++i)
#pragma unroll
        for (int j = 0; j < 8; ++j)
#pragma unroll
            for (int q = 0; q < 4; ++q) acc[i][j][q] = 0.f;

    uint4 Ab[2][2], Bb[2][4];
    Ab[0][0] = pA0[0];
    Ab[0][1] = pA1[0];
#pragma unroll
    for (int j = 0; j < 4; ++j) Bb[0][j] = pB[j * 1024];

#pragma unroll 2
    for (int k16 = 0; k16 < 32; ++k16) {
        int cur = k16 & 1, nxt = cur ^ 1;
        if (k16 < 31) {
            int off = (k16 + 1) * 32;
            Ab[nxt][0] = pA0[off];
            Ab[nxt][1] = pA1[off];
#pragma unroll
            for (int j = 0; j < 4; ++j) Bb[nxt][j] = pB[j * 1024 + off];
        }
#pragma unroll
        for (int n4 = 0; n4 < 4; ++n4) {
            uint4 B4 = Bb[cur][n4];
            mma_f16(acc[0][2 * n4],     Ab[cur][0], B4.x, B4.y);
            mma_f16(acc[0][2 * n4 + 1], Ab[cur][0], B4.z, B4.w);
            mma_f16(acc[1][2 * n4],     Ab[cur][1], B4.x, B4.y);
            mma_f16(acc[1][2 * n4 + 1], Ab[cur][1], B4.z, B4.w);
        }
    }

    __syncthreads();

    float s[4] = {0.f, 0.f, 0.f, 0.f};
#pragma unroll
    for (int nt = 0; nt < 8; ++nt) {
#pragma unroll
        for (int j = 0; j < 2; ++j) {
            int ul = warpN * 64 + nt * 8 + 2 * tg + j;
            float cb = comb_s[ul], vv = v_s[ul];
            s[0] = fmaf(vv, tanh_fast(acc[0][nt][j] + cb), s[0]);
            s[1] = fmaf(vv, tanh_fast(acc[0][nt][2 + j] + cb), s[1]);
            s[2] = fmaf(vv, tanh_fast(acc[1][nt][j] + cb), s[2]);
            s[3] = fmaf(vv, tanh_fast(acc[1][nt][2 + j] + cb), s[3]);
        }
    }
#pragma unroll
    for (int i = 0; i < 4; ++i) {
        s[i] += __shfl_xor_sync(0xffffffffu, s[i], 1);
        s[i] += __shfl_xor_sync(0xffffffffu, s[i], 2);
    }
    if (tg == 0) {
        int rbase = warpM * 32;
        atomicAdd(&srow[rbase + g], s[0]);
        atomicAdd(&srow[rbase + g + 8], s[1]);
        atomicAdd(&srow[rbase + 16 + g], s[2]);
        atomicAdd(&srow[rbase + 16 + g + 8], s[3]);
    }
    __syncthreads();
    if (tid < 128)
        g_spart[(size_t)nchunk * BB * TT + b * TT + t0 + tid] = srow[tid];
}

// ---------------- context: inline stats, 512 threads, t-split warp pairs ----------------
// grid (64 b, 4 kg), 512 threads = 16 warps; warp pair (2w,2w+1) -> k16 = kg*8+w,
// th = wid&1 selects t16 half. Partials combined via small SMEM buffer.
__global__ void __launch_bounds__(512)
ctx_kernel(float* __restrict__ out) {
    int b = blockIdx.x;
    int kg = blockIdx.y;
    int tid = threadIdx.x;
    int wid = tid >> 5, lane = tid & 31;
    int g = lane >> 2, tg = lane & 3;
    int kloc = wid >> 1;                 // 0..7
    int k16 = kg * 8 + kloc;
    int th = wid & 1;                    // t16 half

    __shared__ float w[TT];
    __shared__ float red[512];
    __shared__ float psum[8 * 16];

    // combine score partials + block-wide max
    float m = -INFINITY;
    for (int t = tid; t < TT; t += 512) {
        float sc = g_spart[b * TT + t] + g_spart[BB * TT + b * TT + t];
        w[t] = sc;
        m = fmaxf(m, sc);
    }
    red[tid] = m;
    __syncthreads();
    for (int s = 256; s > 0; s >>= 1) {
        if (tid < s) red[tid] = fmaxf(red[tid], red[tid + s]);
        __syncthreads();
    }
    float mx = red[0];
    __syncthreads();
    float sm = 0.f;
    for (int t = tid; t < TT; t += 512)
        sm += expf(w[t] - mx);
    red[tid] = sm;
    __syncthreads();
    for (int s = 256; s > 0; s >>= 1) {
        if (tid < s) red[tid] += red[tid + s];
        __syncthreads();
    }
    float inv = 1.0f / red[0];
    __syncthreads();
    for (int t = tid; t < TT; t += 512)
        w[t] = expf(w[t] - mx) * inv;
    __syncthreads();

    // weighted reduction over this warp's 64 t16 tiles
    const uint4* pA = g_afrag + (((size_t)(b * 128 + th * 64) * 32 + k16) * 32 + lane);
    const float* wbase = w + (th * 64) * 16;
    float a0 = 0.f, a1 = 0.f, a2 = 0.f, a3 = 0.f;
#pragma unroll 4
    for (int t16 = 0; t16 < 64; ++t16) {
        uint4 v = pA[(size_t)t16 * 1024];
        float wlo = wbase[t16 * 16 + g];
        float whi = wbase[t16 * 16 + 8 + g];
        float2 f;
        f = __half22float2(*(__half2*)&v.x);
        a0 = fmaf(wlo, f.x, a0); a1 = fmaf(wlo, f.y, a1);
        f = __half22float2(*(__half2*)&v.y);
        a0 = fmaf(whi, f.x, a0); a1 = fmaf(whi, f.y, a1);
        f = __half22float2(*(__half2*)&v.z);
        a2 = fmaf(wlo, f.x, a2); a3 = fmaf(wlo, f.y, a3);
        f = __half22float2(*(__half2*)&v.w);
        a2 = fmaf(whi, f.x, a2); a3 = fmaf(whi, f.y, a3);
    }
#pragma unroll
    for (int o = 4; o <= 16; o <<= 1) {
        a0 += __shfl_xor_sync(0xffffffffu, a0, o);
        a1 += __shfl_xor_sync(0xffffffffu, a1, o);
        a2 += __shfl_xor_sync(0xffffffffu, a2, o);
        a3 += __shfl_xor_sync(0xffffffffu, a3, o);
    }
    if (th == 0 && g == 0) {
        int base = kloc * 16;
        psum[base + 2 * tg]     = a0;
        psum[base + 2 * tg + 1] = a1;
        psum[base + 2 * tg + 8] = a2;
        psum[base + 2 * tg + 9] = a3;
    }
    __syncthreads();
    if (th == 1 && g == 0) {
        int base = kloc * 16;
        int d = k16 * 16 + 2 * tg;
        out[b * DD + d]     = psum[base + 2 * tg]     + a0;
        out[b * DD + d + 1] = psum[base + 2 * tg + 1] + a1;
        out[b * DD + d + 8] = psum[base + 2 * tg + 8] + a2;
        out[b * DD + d + 9] = psum[base + 2 * tg + 9] + a3;
    }
}

// ---------------- launch ----------------
extern "C" void kernel_launch(void* const* d_in, const int* in_sizes, int n_in,
                              void* d_out, int out_size) {
    const float* features = (const float*)d_in[0];
    const float* hidden   = (const float*)d_in[1];
    const float* W1_w     = (const float*)d_in[2];
    const float* W1_b     = (const float*)d_in[3];
    const float* W2_w     = (const float*)d_in[4];
    const float* W2_b     = (const float*)d_in[5];
    const float* V_w      = (const float*)d_in[6];
    // V_b: constant shift, softmax-invariant -> dropped
    float* out = (float*)d_out;

    prep_all_kernel<<<32960, 256>>>(features, W1_w, hidden, W2_w, W1_b, W2_b);

    dim3 sgrid(2, 16, BB);
    score_kernel<<<sgrid, 512>>>(V_w);

    dim3 cgrid(BB, 4);
    ctx_kernel<<<cgrid, 512>>>(out);
}

// round 17
// speedup vs baseline: 1.0752x; 1.0752x over previous
#include <cuda_runtime.h>
#include <cuda_fp16.h>
#include <math.h>
#include <stdint.h>

#define BB 64
#define TT 2048
#define DD 512
#define UU 512

// ---------------- device scratch ----------------
__device__ float g_comb[BB * UU];
__device__ float g_spart[2 * BB * TT];
// A fragments: [b][t16 0..127][k16 0..31][lane 0..31] -> uint4 (a0,a1,a2,a3) fp16x2
__device__ uint4 g_afrag[BB * 128 * 32 * 32];
// B fragments (fp16, 2 n8 per uint4): [n4 0..31][k16 0..31][lane 0..31]
__device__ uint4 g_bfrag[32 * 32 * 32];

// ---------------- helpers ----------------
__device__ __forceinline__ uint32_t pack_h2(float x, float y) {
    __half2 h = __floats2half2_rn(x, y);
    return *(uint32_t*)&h;
}

__device__ __forceinline__ float tanh_fast(float x) {
    float y;
    asm("tanh.approx.f32 %0, %1;" : "=f"(y) : "f"(x));
    return y;
}

__device__ __forceinline__ void mma_f16(float* d, const uint4& a, uint32_t b0, uint32_t b1) {
    asm volatile(
        "mma.sync.aligned.m16n8k16.row.col.f32.f16.f16.f32 "
        "{%0,%1,%2,%3}, {%4,%5,%6,%7}, {%8,%9}, {%0,%1,%2,%3};"
        : "+f"(d[0]), "+f"(d[1]), "+f"(d[2]), "+f"(d[3])
        : "r"(a.x), "r"(a.y), "r"(a.z), "r"(a.w), "r"(b0), "r"(b1));
}

// ---------------- prep: features fp32 -> fp16 fragment-major (R12 version) ----------------
__global__ void prep_afrag_kernel(const float* __restrict__ feat) {
    int gidx = blockIdx.x * 256 + threadIdx.x;      // 8388608
    int lane = gidx & 31;
    int k16 = (gidx >> 5) & 31;
    int t16 = (gidx >> 10) & 127;
    int b = gidx >> 17;
    int g = lane >> 2, tg = lane & 3;
    int tA = t16 * 16 + g;
    int kA = k16 * 16 + 2 * tg;
    const float* base = feat + ((size_t)b * TT) * DD;
    float2 f00 = *(const float2*)(base + (size_t)tA * DD + kA);
    float2 f10 = *(const float2*)(base + (size_t)(tA + 8) * DD + kA);
    float2 f01 = *(const float2*)(base + (size_t)tA * DD + kA + 8);
    float2 f11 = *(const float2*)(base + (size_t)(tA + 8) * DD + kA + 8);
    uint4 o;
    o.x = pack_h2(f00.x, f00.y);
    o.y = pack_h2(f10.x, f10.y);
    o.z = pack_h2(f01.x, f01.y);
    o.w = pack_h2(f11.x, f11.y);
    g_afrag[gidx] = o;
}

// ---------------- prep: W1 -> fp16 fragment-major (2 n8 per uint4) ----------------
__global__ void prep_bfrag_kernel(const float* __restrict__ W1) {
    int gidx = blockIdx.x * 256 + threadIdx.x;      // 32768
    int lane = gidx & 31;
    int k16 = (gidx >> 5) & 31;
    int n4 = gidx >> 10;
    int g = lane >> 2, tg = lane & 3;
    int k = k16 * 16 + 2 * tg;
    int ua = (2 * n4) * 8 + g;
    int ub = (2 * n4 + 1) * 8 + g;
    uint4 o;
    o.x = pack_h2(W1[(size_t)k * UU + ua],       W1[(size_t)(k + 1) * UU + ua]);
    o.y = pack_h2(W1[(size_t)(k + 8) * UU + ua], W1[(size_t)(k + 9) * UU + ua]);
    o.z = pack_h2(W1[(size_t)k * UU + ub],       W1[(size_t)(k + 1) * UU + ub]);
    o.w = pack_h2(W1[(size_t)(k + 8) * UU + ub], W1[(size_t)(k + 9) * UU + ub]);
    g_bfrag[gidx] = o;
}

// ---------------- comb[b][u] ----------------
__global__ void comb_kernel(const float* __restrict__ hidden,
                            const float* __restrict__ W2,
                            const float* __restrict__ W1b,
                            const float* __restrict__ W2b) {
    int b = blockIdx.x;
    int u = threadIdx.x;
    __shared__ float h[DD];
    h[u] = hidden[b * DD + u];
    __syncthreads();
    float acc = W1b[u] + W2b[u];
#pragma unroll 8
    for (int d = 0; d < DD; ++d)
        acc = fmaf(h[d], W2[d * UU + u], acc);
    g_comb[b * UU + u] = acc;
}

// ---------------- score GEMM: R12 winner (byte-identical) ----------------
__global__ void __launch_bounds__(512)
score_kernel(const float* __restrict__ Vw) {
    __shared__ float comb_s[256];
    __shared__ float v_s[256];
    __shared__ float srow[128];

    int tid = threadIdx.x;
    int wid = tid >> 5, lane = tid & 31;
    int warpM = wid & 3, warpN = wid >> 2;
    int g = lane >> 2, tg = lane & 3;

    int nchunk = blockIdx.x;
    int t0 = blockIdx.y << 7;
    int b = blockIdx.z;
    int u0 = nchunk << 8;

    if (tid < 256) {
        comb_s[tid] = g_comb[b * UU + u0 + tid];
        v_s[tid] = Vw[u0 + tid];
    }
    if (tid < 128) srow[tid] = 0.f;

    int tt0 = (t0 >> 4) + warpM * 2;
    const uint4* pA0 = g_afrag + (((size_t)(b * 128 + tt0) * 32) * 32 + lane);
    const uint4* pA1 = pA0 + 32 * 32;
    const uint4* pB  = g_bfrag + (((size_t)(nchunk * 16 + warpN * 4) * 32) * 32 + lane);

    float acc[2][8][4];
#pragma unroll
    for (int i = 0; i < 2; ++i)
#pragma unroll
        for (int j = 0; j < 8; ++j)
#pragma unroll
            for (int q = 0; q < 4; ++q) acc[i][j][q] = 0.f;

    uint4 Ab[2][2], Bb[2][4];
    Ab[0][0] = pA0[0];
    Ab[0][1] = pA1[0];
#pragma unroll
    for (int j = 0; j < 4; ++j) Bb[0][j] = pB[j * 1024];

#pragma unroll 2
    for (int k16 = 0; k16 < 32; ++k16) {
        int cur = k16 & 1, nxt = cur ^ 1;
        if (k16 < 31) {
            int off = (k16 + 1) * 32;
            Ab[nxt][0] = pA0[off];
            Ab[nxt][1] = pA1[off];
#pragma unroll
            for (int j = 0; j < 4; ++j) Bb[nxt][j] = pB[j * 1024 + off];
        }
#pragma unroll
        for (int n4 = 0; n4 < 4; ++n4) {
            uint4 B4 = Bb[cur][n4];
            mma_f16(acc[0][2 * n4],     Ab[cur][0], B4.x, B4.y);
            mma_f16(acc[0][2 * n4 + 1], Ab[cur][0], B4.z, B4.w);
            mma_f16(acc[1][2 * n4],     Ab[cur][1], B4.x, B4.y);
            mma_f16(acc[1][2 * n4 + 1], Ab[cur][1], B4.z, B4.w);
        }
    }

    __syncthreads();

    float s[4] = {0.f, 0.f, 0.f, 0.f};
#pragma unroll
    for (int nt = 0; nt < 8; ++nt) {
#pragma unroll
        for (int j = 0; j < 2; ++j) {
            int ul = warpN * 64 + nt * 8 + 2 * tg + j;
            float cb = comb_s[ul], vv = v_s[ul];
            s[0] = fmaf(vv, tanh_fast(acc[0][nt][j] + cb), s[0]);
            s[1] = fmaf(vv, tanh_fast(acc[0][nt][2 + j] + cb), s[1]);
            s[2] = fmaf(vv, tanh_fast(acc[1][nt][j] + cb), s[2]);
            s[3] = fmaf(vv, tanh_fast(acc[1][nt][2 + j] + cb), s[3]);
        }
    }
#pragma unroll
    for (int i = 0; i < 4; ++i) {
        s[i] += __shfl_xor_sync(0xffffffffu, s[i], 1);
        s[i] += __shfl_xor_sync(0xffffffffu, s[i], 2);
    }
    if (tg == 0) {
        int rbase = warpM * 32;
        atomicAdd(&srow[rbase + g], s[0]);
        atomicAdd(&srow[rbase + g + 8], s[1]);
        atomicAdd(&srow[rbase + 16 + g], s[2]);
        atomicAdd(&srow[rbase + 16 + g + 8], s[3]);
    }
    __syncthreads();
    if (tid < 128)
        g_spart[(size_t)nchunk * BB * TT + b * TT + t0 + tid] = srow[tid];
}

// ---------------- context: inline stats, 512 threads, t-split warp pairs (R16 version) ----------------
// grid (64 b, 4 kg), 512 threads = 16 warps; warp pair (2w,2w+1) -> k16 = kg*8+kloc,
// th = wid&1 selects t16 half. Partials combined via small SMEM buffer.
__global__ void __launch_bounds__(512)
ctx_kernel(float* __restrict__ out) {
    int b = blockIdx.x;
    int kg = blockIdx.y;
    int tid = threadIdx.x;
    int wid = tid >> 5, lane = tid & 31;
    int g = lane >> 2, tg = lane & 3;
    int kloc = wid >> 1;                 // 0..7
    int k16 = kg * 8 + kloc;
    int th = wid & 1;                    // t16 half

    __shared__ float w[TT];
    __shared__ float red[512];
    __shared__ float psum[8 * 16];

    // combine score partials + block-wide max
    float m = -INFINITY;
    for (int t = tid; t < TT; t += 512) {
        float sc = g_spart[b * TT + t] + g_spart[BB * TT + b * TT + t];
        w[t] = sc;
        m = fmaxf(m, sc);
    }
    red[tid] = m;
    __syncthreads();
    for (int s = 256; s > 0; s >>= 1) {
        if (tid < s) red[tid] = fmaxf(red[tid], red[tid + s]);
        __syncthreads();
    }
    float mx = red[0];
    __syncthreads();
    float sm = 0.f;
    for (int t = tid; t < TT; t += 512)
        sm += expf(w[t] - mx);
    red[tid] = sm;
    __syncthreads();
    for (int s = 256; s > 0; s >>= 1) {
        if (tid < s) red[tid] += red[tid + s];
        __syncthreads();
    }
    float inv = 1.0f / red[0];
    __syncthreads();
    for (int t = tid; t < TT; t += 512)
        w[t] = expf(w[t] - mx) * inv;
    __syncthreads();

    // weighted reduction over this warp's 64 t16 tiles
    const uint4* pA = g_afrag + (((size_t)(b * 128 + th * 64) * 32 + k16) * 32 + lane);
    const float* wbase = w + (th * 64) * 16;
    float a0 = 0.f, a1 = 0.f, a2 = 0.f, a3 = 0.f;
#pragma unroll 4
    for (int t16 = 0; t16 < 64; ++t16) {
        uint4 v = pA[(size_t)t16 * 1024];
        float wlo = wbase[t16 * 16 + g];
        float whi = wbase[t16 * 16 + 8 + g];
        float2 f;
        f = __half22float2(*(__half2*)&v.x);
        a0 = fmaf(wlo, f.x, a0); a1 = fmaf(wlo, f.y, a1);
        f = __half22float2(*(__half2*)&v.y);
        a0 = fmaf(whi, f.x, a0); a1 = fmaf(whi, f.y, a1);
        f = __half22float2(*(__half2*)&v.z);
        a2 = fmaf(wlo, f.x, a2); a3 = fmaf(wlo, f.y, a3);
        f = __half22float2(*(__half2*)&v.w);
        a2 = fmaf(whi, f.x, a2); a3 = fmaf(whi, f.y, a3);
    }
#pragma unroll
    for (int o = 4; o <= 16; o <<= 1) {
        a0 += __shfl_xor_sync(0xffffffffu, a0, o);
        a1 += __shfl_xor_sync(0xffffffffu, a1, o);
        a2 += __shfl_xor_sync(0xffffffffu, a2, o);
        a3 += __shfl_xor_sync(0xffffffffu, a3, o);
    }
    if (th == 0 && g == 0) {
        int base = kloc * 16;
        psum[base + 2 * tg]     = a0;
        psum[base + 2 * tg + 1] = a1;
        psum[base + 2 * tg + 8] = a2;
        psum[base + 2 * tg + 9] = a3;
    }
    __syncthreads();
    if (th == 1 && g == 0) {
        int base = kloc * 16;
        int d = k16 * 16 + 2 * tg;
        out[b * DD + d]     = psum[base + 2 * tg]     + a0;
        out[b * DD + d + 1] = psum[base + 2 * tg + 1] + a1;
        out[b * DD + d + 8] = psum[base + 2 * tg + 8] + a2;
        out[b * DD + d + 9] = psum[base + 2 * tg + 9] + a3;
    }
}

// ---------------- launch ----------------
extern "C" void kernel_launch(void* const* d_in, const int* in_sizes, int n_in,
                              void* d_out, int out_size) {
    const float* features = (const float*)d_in[0];
    const float* hidden   = (const float*)d_in[1];
    const float* W1_w     = (const float*)d_in[2];
    const float* W1_b     = (const float*)d_in[3];
    const float* W2_w     = (const float*)d_in[4];
    const float* W2_b     = (const float*)d_in[5];
    const float* V_w      = (const float*)d_in[6];
    // V_b: constant shift, softmax-invariant -> dropped
    float* out = (float*)d_out;

    prep_afrag_kernel<<<BB * 128 * 32 * 32 / 256, 256>>>(features);
    prep_bfrag_kernel<<<32 * 32 * 32 / 256, 256>>>(W1_w);
    comb_kernel<<<BB, UU>>>(hidden, W2_w, W1_b, W2_b);

    dim3 sgrid(2, 16, BB);
    score_kernel<<<sgrid, 512>>>(V_w);

    dim3 cgrid(BB, 4);
    ctx_kernel<<<cgrid, 512>>>(out);
}